// round 2
// baseline (speedup 1.0000x reference)
#include <cuda_runtime.h>
#include <math.h>

#define Bx 4
#define Sx 2048
#define Dx 1024
#define Hx 16
#define HDx 64
#define Mx (Bx*Sx)   // 8192

// Scratch (allocation-free rule: __device__ globals)
__device__ float g_q[Bx*Hx*Sx*HDx];
__device__ float g_k[Bx*Hx*Sx*HDx];
__device__ float g_v[Bx*Hx*Sx*HDx];
__device__ float g_o[Bx*Hx*Sx*HDx];

// ---------------------------------------------------------------------------
// QKV projection: q[b,h,s,e] = x[b,s,:] @ Wq[h] + bq[h]   (and k, v)
// One block = 64 rows x one head (64 cols). blockIdx.z selects q/k/v.
// ---------------------------------------------------------------------------
__global__ __launch_bounds__(256) void qkv_kernel(
    const float* __restrict__ x,
    const float* __restrict__ Wq, const float* __restrict__ bq,
    const float* __restrict__ Wk, const float* __restrict__ bk,
    const float* __restrict__ Wv, const float* __restrict__ bv)
{
    const float* W; const float* bias; float* out;
    if (blockIdx.z == 0)      { W = Wq; bias = bq; out = g_q; }
    else if (blockIdx.z == 1) { W = Wk; bias = bk; out = g_k; }
    else                      { W = Wv; bias = bv; out = g_v; }

    const int h  = blockIdx.y;
    const int m0 = blockIdx.x * 64;

    __shared__ float As[16][64];   // [k][m]
    __shared__ float Bs[16][64];   // [k][n]

    const int tid = threadIdx.x;
    const int tx = tid & 15, ty = tid >> 4;
    const int ar = tid >> 2, ac = (tid & 3) << 2;        // A loader: row, kcol
    const int br = tid >> 4, bn = (tid & 15) << 2;       // B loader: krow, ncol

    const float* Wh = W + (size_t)h * Dx * HDx;

    float acc[4][4];
    #pragma unroll
    for (int i = 0; i < 4; i++)
        #pragma unroll
        for (int j = 0; j < 4; j++) acc[i][j] = 0.f;

    for (int k0 = 0; k0 < Dx; k0 += 16) {
        float4 a4 = *(const float4*)(x  + (size_t)(m0 + ar) * Dx + k0 + ac);
        float4 b4 = *(const float4*)(Wh + (size_t)(k0 + br) * HDx + bn);
        As[ac + 0][ar] = a4.x; As[ac + 1][ar] = a4.y;
        As[ac + 2][ar] = a4.z; As[ac + 3][ar] = a4.w;
        *(float4*)&Bs[br][bn] = b4;
        __syncthreads();
        #pragma unroll
        for (int kk = 0; kk < 16; kk++) {
            float4 a = *(const float4*)&As[kk][ty << 2];
            float4 b = *(const float4*)&Bs[kk][tx << 2];
            float av[4] = {a.x, a.y, a.z, a.w};
            float bv4[4] = {b.x, b.y, b.z, b.w};
            #pragma unroll
            for (int i = 0; i < 4; i++)
                #pragma unroll
                for (int j = 0; j < 4; j++)
                    acc[i][j] += av[i] * bv4[j];
        }
        __syncthreads();
    }

    float bb[4];
    #pragma unroll
    for (int j = 0; j < 4; j++) bb[j] = bias[h * HDx + (tx << 2) + j];
    #pragma unroll
    for (int i = 0; i < 4; i++) {
        int m = m0 + (ty << 2) + i;
        int b = m >> 11;         // / 2048
        int s = m & 2047;
        float* op = out + ((size_t)(b * Hx + h) * Sx + s) * HDx + (tx << 2);
        *(float4*)op = make_float4(acc[i][0] + bb[0], acc[i][1] + bb[1],
                                   acc[i][2] + bb[2], acc[i][3] + bb[3]);
    }
}

// ---------------------------------------------------------------------------
// Causal flash attention, fp32. One block = 64 query rows of one (b,h).
// smem: Qs/Ks transposed [dim][row] for float4 fragment loads; Vs natural.
// Ps (softmax staging for the PV GEMM) ALIASES Ks — Ks is dead after the
// S = QK^T GEMM. Total 3 x 16KB = 48KB static smem (no dynamic opt-in).
// ---------------------------------------------------------------------------
__global__ __launch_bounds__(256) void attn_kernel()
{
    __shared__ float Qs[4096];   // [64 dim][64 row]
    __shared__ float Ks[4096];   // [64 dim][64 col]; reused as Ps [64 row][64 kv]
    __shared__ float Vs[4096];   // [64 kv ][64 dim]
    float* Ps = Ks;

    const int bh = blockIdx.y;     // b*H + h
    const int qt = blockIdx.x;     // query tile
    const int tid = threadIdx.x;
    const int tx = tid & 15, ty = tid >> 4;

    const float* Q = g_q + (size_t)bh * Sx * HDx + (size_t)qt * 64 * HDx;
    const float* K = g_k + (size_t)bh * Sx * HDx;
    const float* V = g_v + (size_t)bh * Sx * HDx;

    // Load Q tile transposed (conflict-free stores: lane -> distinct row)
    {
        int r = tid & 63;
        int g = tid >> 6;                       // 0..3
        #pragma unroll
        for (int it = 0; it < 4; it++) {
            int e0 = (g + it * 4) * 4;          // 0..60, unique per (g,it)
            float4 v = *(const float4*)(Q + r * HDx + e0);
            Qs[(e0 + 0) * 64 + r] = v.x;
            Qs[(e0 + 1) * 64 + r] = v.y;
            Qs[(e0 + 2) * 64 + r] = v.z;
            Qs[(e0 + 3) * 64 + r] = v.w;
        }
    }

    float m_i[4], l_i[4], o[4][4];
    #pragma unroll
    for (int i = 0; i < 4; i++) {
        m_i[i] = -3.0e38f; l_i[i] = 0.f;
        #pragma unroll
        for (int j = 0; j < 4; j++) o[i][j] = 0.f;
    }

    for (int jt = 0; jt <= qt; jt++) {
        __syncthreads();   // previous PV done before overwriting K(=Ps)/V
        {
            int r = tid & 63;
            int g = tid >> 6;
            const float* Kp = K + (size_t)(jt * 64 + r) * HDx;
            #pragma unroll
            for (int it = 0; it < 4; it++) {
                int e0 = (g + it * 4) * 4;
                float4 v = *(const float4*)(Kp + e0);
                Ks[(e0 + 0) * 64 + r] = v.x;
                Ks[(e0 + 1) * 64 + r] = v.y;
                Ks[(e0 + 2) * 64 + r] = v.z;
                Ks[(e0 + 3) * 64 + r] = v.w;
            }
            const float* Vp = V + (size_t)jt * 64 * HDx;
            #pragma unroll
            for (int it = 0; it < 4; it++) {
                int idx = tid + it * 256;       // float4 index 0..1023
                *(float4*)&Vs[idx * 4] = *(const float4*)(Vp + idx * 4);
            }
        }
        __syncthreads();

        // S = Q K^T (64x64), each thread 4x4
        float s[4][4];
        #pragma unroll
        for (int i = 0; i < 4; i++)
            #pragma unroll
            for (int j = 0; j < 4; j++) s[i][j] = 0.f;

        #pragma unroll 8
        for (int kk = 0; kk < 64; kk++) {
            float4 a = *(const float4*)&Qs[kk * 64 + (ty << 2)];
            float4 b = *(const float4*)&Ks[kk * 64 + (tx << 2)];
            float av[4] = {a.x, a.y, a.z, a.w};
            float bv4[4] = {b.x, b.y, b.z, b.w};
            #pragma unroll
            for (int i = 0; i < 4; i++)
                #pragma unroll
                for (int j = 0; j < 4; j++)
                    s[i][j] += av[i] * bv4[j];
        }

        const float scale = 0.125f;  // 1/sqrt(64)
        if (jt == qt) {
            #pragma unroll
            for (int i = 0; i < 4; i++)
                #pragma unroll
                for (int j = 0; j < 4; j++) {
                    int row = (ty << 2) + i, col = (tx << 2) + j;
                    s[i][j] = (col <= row) ? s[i][j] * scale : -3.0e38f;
                }
        } else {
            #pragma unroll
            for (int i = 0; i < 4; i++)
                #pragma unroll
                for (int j = 0; j < 4; j++) s[i][j] *= scale;
        }

        // Online softmax update; row stats reduced across the 16-lane tx group
        #pragma unroll
        for (int i = 0; i < 4; i++) {
            float tm = fmaxf(fmaxf(s[i][0], s[i][1]), fmaxf(s[i][2], s[i][3]));
            #pragma unroll
            for (int off = 8; off > 0; off >>= 1)
                tm = fmaxf(tm, __shfl_xor_sync(0xffffffffu, tm, off));
            float mn = fmaxf(m_i[i], tm);
            float f  = __expf(m_i[i] - mn);
            m_i[i] = mn;
            float rs = 0.f;
            #pragma unroll
            for (int j = 0; j < 4; j++) {
                s[i][j] = __expf(s[i][j] - mn);
                rs += s[i][j];
            }
            #pragma unroll
            for (int off = 8; off > 0; off >>= 1)
                rs += __shfl_xor_sync(0xffffffffu, rs, off);
            l_i[i] = l_i[i] * f + rs;
            #pragma unroll
            for (int j = 0; j < 4; j++) o[i][j] *= f;
        }

        // All threads must be done READING Ks before Ps (same memory) is written
        __syncthreads();

        // Stage P for the PV GEMM
        #pragma unroll
        for (int i = 0; i < 4; i++)
            *(float4*)&Ps[((ty << 2) + i) * 64 + (tx << 2)] =
                make_float4(s[i][0], s[i][1], s[i][2], s[i][3]);
        __syncthreads();

        // O += P V
        #pragma unroll 8
        for (int kk = 0; kk < 64; kk++) {
            float a0 = Ps[((ty << 2) + 0) * 64 + kk];
            float a1 = Ps[((ty << 2) + 1) * 64 + kk];
            float a2 = Ps[((ty << 2) + 2) * 64 + kk];
            float a3 = Ps[((ty << 2) + 3) * 64 + kk];
            float4 b = *(const float4*)&Vs[kk * 64 + (tx << 2)];
            float bv4[4] = {b.x, b.y, b.z, b.w};
            #pragma unroll
            for (int j = 0; j < 4; j++) {
                o[0][j] += a0 * bv4[j];
                o[1][j] += a1 * bv4[j];
                o[2][j] += a2 * bv4[j];
                o[3][j] += a3 * bv4[j];
            }
        }
    }

    float* O = g_o + (size_t)bh * Sx * HDx + (size_t)qt * 64 * HDx;
    #pragma unroll
    for (int i = 0; i < 4; i++) {
        float inv = 1.f / l_i[i];
        int row = (ty << 2) + i;
        *(float4*)&O[row * HDx + (tx << 2)] =
            make_float4(o[i][0] * inv, o[i][1] * inv, o[i][2] * inv, o[i][3] * inv);
    }
}

// ---------------------------------------------------------------------------
// Output projection: out[b,s,:] = concat_heads(o)[b,s,:] @ Wp + bp
// A is read head-interleaved straight out of g_o's [B,H,S,HD] layout.
// ---------------------------------------------------------------------------
__global__ __launch_bounds__(256) void proj_kernel(
    const float* __restrict__ Wp, const float* __restrict__ bp,
    float* __restrict__ out)
{
    const int m0 = blockIdx.x * 64;
    const int n0 = blockIdx.y * 64;

    __shared__ float As[16][64];
    __shared__ float Bs[16][64];

    const int tid = threadIdx.x;
    const int tx = tid & 15, ty = tid >> 4;
    const int ar = tid >> 2, ac = (tid & 3) << 2;
    const int br = tid >> 4, bn = (tid & 15) << 2;

    // Fixed per-thread A row decomposition
    const int m = m0 + ar;
    const int b = m >> 11;
    const int s = m & 2047;

    float acc[4][4];
    #pragma unroll
    for (int i = 0; i < 4; i++)
        #pragma unroll
        for (int j = 0; j < 4; j++) acc[i][j] = 0.f;

    for (int k0 = 0; k0 < Dx; k0 += 16) {
        int k = k0 + ac;
        int h = k >> 6;        // head
        int e = k & 63;        // dim within head (float4-aligned, stays in-head)
        float4 a4 = *(const float4*)&g_o[((size_t)(b * Hx + h) * Sx + s) * HDx + e];
        float4 b4 = *(const float4*)&Wp[(size_t)(k0 + br) * Dx + n0 + bn];
        As[ac + 0][ar] = a4.x; As[ac + 1][ar] = a4.y;
        As[ac + 2][ar] = a4.z; As[ac + 3][ar] = a4.w;
        *(float4*)&Bs[br][bn] = b4;
        __syncthreads();
        #pragma unroll
        for (int kk = 0; kk < 16; kk++) {
            float4 a = *(const float4*)&As[kk][ty << 2];
            float4 bb = *(const float4*)&Bs[kk][tx << 2];
            float av[4] = {a.x, a.y, a.z, a.w};
            float bv4[4] = {bb.x, bb.y, bb.z, bb.w};
            #pragma unroll
            for (int i = 0; i < 4; i++)
                #pragma unroll
                for (int j = 0; j < 4; j++)
                    acc[i][j] += av[i] * bv4[j];
        }
        __syncthreads();
    }

    float bb[4];
    #pragma unroll
    for (int j = 0; j < 4; j++) bb[j] = bp[n0 + (tx << 2) + j];
    #pragma unroll
    for (int i = 0; i < 4; i++) {
        int mr = m0 + (ty << 2) + i;
        *(float4*)&out[(size_t)mr * Dx + n0 + (tx << 2)] =
            make_float4(acc[i][0] + bb[0], acc[i][1] + bb[1],
                        acc[i][2] + bb[2], acc[i][3] + bb[3]);
    }
}

// ---------------------------------------------------------------------------
extern "C" void kernel_launch(void* const* d_in, const int* in_sizes, int n_in,
                              void* d_out, int out_size)
{
    const float* x  = (const float*)d_in[0];
    const float* Wq = (const float*)d_in[1];
    const float* bq = (const float*)d_in[2];
    const float* Wk = (const float*)d_in[3];
    const float* bk = (const float*)d_in[4];
    const float* Wv = (const float*)d_in[5];
    const float* bv = (const float*)d_in[6];
    const float* Wp = (const float*)d_in[7];
    const float* bp = (const float*)d_in[8];
    float* out = (float*)d_out;

    qkv_kernel<<<dim3(Mx / 64, Hx, 3), 256>>>(x, Wq, bq, Wk, bk, Wv, bv);
    attn_kernel<<<dim3(Sx / 64, Bx * Hx), 256>>>();
    proj_kernel<<<dim3(Mx / 64, Dx / 64), 256>>>(Wp, bp, out);
}

// round 3
// speedup vs baseline: 2.7515x; 2.7515x over previous
#include <cuda_runtime.h>
#include <cuda_bf16.h>

#define Bx 4
#define Sx 2048
#define Dx 1024
#define Hx 16
#define HDx 64
#define Mx (Bx*Sx)          // 8192
#define NN (Bx*Hx*Sx*HDx)   // 8388608

// Split bf16 intermediates (hi + lo ≈ fp32 to ~2^-17)
__device__ __nv_bfloat16 g_qh[NN], g_ql[NN];
__device__ __nv_bfloat16 g_kh[NN], g_kl[NN];
__device__ __nv_bfloat16 g_vh[NN], g_vl[NN];
__device__ __nv_bfloat16 g_oh[NN], g_ol[NN];

// ---------------------------------------------------------------------------
// helpers
// ---------------------------------------------------------------------------
__device__ __forceinline__ unsigned smem_u32(const void* p){
    return (unsigned)__cvta_generic_to_shared(p);
}
__device__ __forceinline__ void ldsm_x4(unsigned& r0, unsigned& r1, unsigned& r2, unsigned& r3, const void* p){
    unsigned a = smem_u32(p);
    asm volatile("ldmatrix.sync.aligned.m8n8.x4.shared.b16 {%0,%1,%2,%3},[%4];\n"
        : "=r"(r0),"=r"(r1),"=r"(r2),"=r"(r3) : "r"(a));
}
__device__ __forceinline__ void ldsm_x4t(unsigned& r0, unsigned& r1, unsigned& r2, unsigned& r3, const void* p){
    unsigned a = smem_u32(p);
    asm volatile("ldmatrix.sync.aligned.m8n8.x4.trans.shared.b16 {%0,%1,%2,%3},[%4];\n"
        : "=r"(r0),"=r"(r1),"=r"(r2),"=r"(r3) : "r"(a));
}
__device__ __forceinline__ void mma_bf16(float c[4], const unsigned a[4], unsigned b0, unsigned b1){
    asm volatile("mma.sync.aligned.m16n8k16.row.col.f32.bf16.bf16.f32 "
        "{%0,%1,%2,%3},{%4,%5,%6,%7},{%8,%9},{%0,%1,%2,%3};\n"
        : "+f"(c[0]),"+f"(c[1]),"+f"(c[2]),"+f"(c[3])
        : "r"(a[0]),"r"(a[1]),"r"(a[2]),"r"(a[3]),"r"(b0),"r"(b1));
}
// (a,b) -> packed bf16x2 hi pair + residual lo pair
__device__ __forceinline__ void split_pack2(float a, float b, unsigned& hi, unsigned& lo){
    __nv_bfloat16 ha = __float2bfloat16(a), hb = __float2bfloat16(b);
    float la = a - __bfloat162float(ha);
    float lb = b - __bfloat162float(hb);
    __nv_bfloat162 h; h.x = ha; h.y = hb;
    __nv_bfloat162 l = __floats2bfloat162_rn(la, lb);
    hi = *reinterpret_cast<unsigned*>(&h);
    lo = *reinterpret_cast<unsigned*>(&l);
}
__device__ __forceinline__ void split_store4(__nv_bfloat16* ph, __nv_bfloat16* pl, float4 v){
    unsigned h0,l0,h1,l1;
    split_pack2(v.x, v.y, h0, l0);
    split_pack2(v.z, v.w, h1, l1);
    *reinterpret_cast<unsigned*>(ph)     = h0;
    *reinterpret_cast<unsigned*>(ph + 2) = h1;
    *reinterpret_cast<unsigned*>(pl)     = l0;
    *reinterpret_cast<unsigned*>(pl + 2) = l1;
}

#define XST 40   // A-tile smem row stride (32 + 8 pad) bf16
#define WST 72   // B-tile smem row stride (64 + 8 pad) bf16

// ---------------------------------------------------------------------------
// Fused QKV: per block = 128 x-rows x one head; q,k,v share the x tile.
// D = (Xhi+Xlo)(Whi+Wlo) via 3 MMAs (hi*hi + hi*lo + lo*hi).
// Outputs stored as split bf16 pairs in [B,H,S,HD] layout.
// ---------------------------------------------------------------------------
__global__ __launch_bounds__(256) void qkv_mma(
    const float* __restrict__ x,
    const float* __restrict__ Wq, const float* __restrict__ bq,
    const float* __restrict__ Wk, const float* __restrict__ bk,
    const float* __restrict__ Wv, const float* __restrict__ bv)
{
    __shared__ __nv_bfloat16 Xh[128*XST], Xl[128*XST];
    __shared__ __nv_bfloat16 Wsh[3][32*WST], Wsl[3][32*WST];

    const int h  = blockIdx.y;
    const int m0 = blockIdx.x * 128;
    const int tid = threadIdx.x;
    const int lane = tid & 31, wid = tid >> 5;
    const int wm = (wid >> 1) * 32, wn = (wid & 1) * 32;   // 4x2 warp grid, 32x32 warp tile

    const float* Wm[3] = { Wq + (size_t)h*Dx*HDx, Wk + (size_t)h*Dx*HDx, Wv + (size_t)h*Dx*HDx };

    float acc[3][2][4][4];
    #pragma unroll
    for (int a=0;a<3;a++){
        #pragma unroll
        for (int b=0;b<2;b++){
            #pragma unroll
            for (int c=0;c<4;c++){
                #pragma unroll
                for (int d=0;d<4;d++) acc[a][b][c][d]=0.f;
            }
        }
    }

    for (int k0 = 0; k0 < Dx; k0 += 32) {
        __syncthreads();
        // X tile 128x32 fp32 -> split
        #pragma unroll
        for (int i = 0; i < 4; i++) {
            int v = tid + i*256;
            int r = v >> 3, c = (v & 7) << 2;
            float4 t = *(const float4*)(x + (size_t)(m0 + r)*Dx + k0 + c);
            split_store4(&Xh[r*XST + c], &Xl[r*XST + c], t);
        }
        // three W tiles 32x64 fp32 -> split
        #pragma unroll
        for (int m = 0; m < 3; m++) {
            #pragma unroll
            for (int i = 0; i < 2; i++) {
                int v = tid + i*256;
                int r = v >> 4, c = (v & 15) << 2;
                float4 t = *(const float4*)(Wm[m] + (size_t)(k0 + r)*HDx + c);
                split_store4(&Wsh[m][r*WST + c], &Wsl[m][r*WST + c], t);
            }
        }
        __syncthreads();

        #pragma unroll
        for (int ks = 0; ks < 32; ks += 16) {
            unsigned ah[2][4], al[2][4];
            #pragma unroll
            for (int mi = 0; mi < 2; mi++) {
                int row = wm + mi*16 + (lane & 15);
                int col = ks + ((lane >> 4) << 3);
                ldsm_x4(ah[mi][0],ah[mi][1],ah[mi][2],ah[mi][3], &Xh[row*XST + col]);
                ldsm_x4(al[mi][0],al[mi][1],al[mi][2],al[mi][3], &Xl[row*XST + col]);
            }
            #pragma unroll
            for (int m = 0; m < 3; m++) {
                unsigned bh[4][2], bl[4][2];
                #pragma unroll
                for (int np = 0; np < 2; np++) {
                    int row = ks + (lane & 15);
                    int col = wn + np*16 + ((lane >> 4) << 3);
                    unsigned r0,r1,r2,r3;
                    ldsm_x4t(r0,r1,r2,r3, &Wsh[m][row*WST + col]);
                    bh[np*2][0]=r0; bh[np*2][1]=r1; bh[np*2+1][0]=r2; bh[np*2+1][1]=r3;
                    ldsm_x4t(r0,r1,r2,r3, &Wsl[m][row*WST + col]);
                    bl[np*2][0]=r0; bl[np*2][1]=r1; bl[np*2+1][0]=r2; bl[np*2+1][1]=r3;
                }
                #pragma unroll
                for (int mi = 0; mi < 2; mi++) {
                    #pragma unroll
                    for (int nf = 0; nf < 4; nf++) {
                        mma_bf16(acc[m][mi][nf], ah[mi], bh[nf][0], bh[nf][1]);
                        mma_bf16(acc[m][mi][nf], ah[mi], bl[nf][0], bl[nf][1]);
                        mma_bf16(acc[m][mi][nf], al[mi], bh[nf][0], bh[nf][1]);
                    }
                }
            }
        }
    }

    const float* bias[3] = { bq + h*HDx, bk + h*HDx, bv + h*HDx };
    __nv_bfloat16* outh[3] = { g_qh, g_kh, g_vh };
    __nv_bfloat16* outl[3] = { g_ql, g_kl, g_vl };
    #pragma unroll
    for (int m = 0; m < 3; m++) {
        #pragma unroll
        for (int mi = 0; mi < 2; mi++) {
            int row = m0 + wm + mi*16 + (lane >> 2);
            #pragma unroll
            for (int half = 0; half < 2; half++) {
                int r = row + half*8;
                int b = r >> 11, s = r & 2047;
                size_t base = ((size_t)(b*Hx + h)*Sx + s)*HDx;
                #pragma unroll
                for (int nf = 0; nf < 4; nf++) {
                    int col = wn + nf*8 + 2*(lane & 3);
                    float v0 = acc[m][mi][nf][half*2+0] + bias[m][col];
                    float v1 = acc[m][mi][nf][half*2+1] + bias[m][col+1];
                    unsigned hi, lo;
                    split_pack2(v0, v1, hi, lo);
                    *reinterpret_cast<unsigned*>(outh[m] + base + col) = hi;
                    *reinterpret_cast<unsigned*>(outl[m] + base + col) = lo;
                }
            }
        }
    }
}

// ---------------------------------------------------------------------------
// Causal flash attention on tensor cores. Block = 64 q-rows of one (b,h),
// 4 warps x 16 q-rows. Q fragments persistent in registers; K via non-trans
// ldmatrix (B operand of QK^T), V via trans ldmatrix; P stays in registers
// (C-frag of QK^T re-packed as A-frag of PV).
// ---------------------------------------------------------------------------
#define KST 72

__global__ __launch_bounds__(128) void attn_mma()
{
    __shared__ __nv_bfloat16 Kh[64*KST], Kl[64*KST], Vh[64*KST], Vl[64*KST];

    const int bh = blockIdx.y, qt = blockIdx.x;
    const int tid = threadIdx.x;
    const int lane = tid & 31, wid = tid >> 5;
    const int qrow0 = qt*64 + wid*16;           // global q row base of this warp

    const __nv_bfloat16* Qh  = g_qh + (size_t)bh*Sx*HDx;
    const __nv_bfloat16* Ql  = g_ql + (size_t)bh*Sx*HDx;
    const __nv_bfloat16* Kgh = g_kh + (size_t)bh*Sx*HDx;
    const __nv_bfloat16* Kgl = g_kl + (size_t)bh*Sx*HDx;
    const __nv_bfloat16* Vgh = g_vh + (size_t)bh*Sx*HDx;
    const __nv_bfloat16* Vgl = g_vl + (size_t)bh*Sx*HDx;

    // persistent Q fragments: 4 k-steps (hd=64)
    unsigned aqh[4][4], aql[4][4];
    {
        int r = lane >> 2, c = 2*(lane & 3);
        #pragma unroll
        for (int ks = 0; ks < 4; ks++) {
            aqh[ks][0] = *(const unsigned*)(Qh + (size_t)(qrow0 + r    )*HDx + ks*16 + c);
            aqh[ks][1] = *(const unsigned*)(Qh + (size_t)(qrow0 + r + 8)*HDx + ks*16 + c);
            aqh[ks][2] = *(const unsigned*)(Qh + (size_t)(qrow0 + r    )*HDx + ks*16 + 8 + c);
            aqh[ks][3] = *(const unsigned*)(Qh + (size_t)(qrow0 + r + 8)*HDx + ks*16 + 8 + c);
            aql[ks][0] = *(const unsigned*)(Ql + (size_t)(qrow0 + r    )*HDx + ks*16 + c);
            aql[ks][1] = *(const unsigned*)(Ql + (size_t)(qrow0 + r + 8)*HDx + ks*16 + c);
            aql[ks][2] = *(const unsigned*)(Ql + (size_t)(qrow0 + r    )*HDx + ks*16 + 8 + c);
            aql[ks][3] = *(const unsigned*)(Ql + (size_t)(qrow0 + r + 8)*HDx + ks*16 + 8 + c);
        }
    }

    float m_i[2] = {-1e30f, -1e30f}, l_i[2] = {0.f, 0.f};
    float o[8][4];
    #pragma unroll
    for (int i=0;i<8;i++){
        #pragma unroll
        for (int j=0;j<4;j++) o[i][j]=0.f;
    }

    for (int jt = 0; jt <= qt; jt++) {
        __syncthreads();
        {
            const __nv_bfloat16* kh = Kgh + (size_t)jt*64*HDx;
            const __nv_bfloat16* kl = Kgl + (size_t)jt*64*HDx;
            const __nv_bfloat16* vh = Vgh + (size_t)jt*64*HDx;
            const __nv_bfloat16* vl = Vgl + (size_t)jt*64*HDx;
            #pragma unroll
            for (int i = 0; i < 4; i++) {
                int v = tid + i*128;               // 0..511
                int r = v >> 3, c = (v & 7) << 3;  // 8 bf16 per float4
                *(float4*)&Kh[r*KST + c] = *(const float4*)(kh + r*HDx + c);
                *(float4*)&Kl[r*KST + c] = *(const float4*)(kl + r*HDx + c);
                *(float4*)&Vh[r*KST + c] = *(const float4*)(vh + r*HDx + c);
                *(float4*)&Vl[r*KST + c] = *(const float4*)(vl + r*HDx + c);
            }
        }
        __syncthreads();

        // S = Q K^T  (16 x 64 per warp)
        float s[8][4];
        #pragma unroll
        for (int i=0;i<8;i++){
            #pragma unroll
            for (int j=0;j<4;j++) s[i][j]=0.f;
        }
        #pragma unroll
        for (int ks = 0; ks < 4; ks++) {
            #pragma unroll
            for (int np = 0; np < 4; np++) {
                int row = np*16 + (lane & 15);            // kv index
                int col = ks*16 + ((lane >> 4) << 3);     // hd index
                unsigned h0,h1,h2,h3,l0,l1,l2,l3;
                ldsm_x4(h0,h1,h2,h3, &Kh[row*KST + col]); // r0=b0[2np] r1=b0[2np+1] r2=b1[2np] r3=b1[2np+1]
                ldsm_x4(l0,l1,l2,l3, &Kl[row*KST + col]);
                mma_bf16(s[np*2],   aqh[ks], h0, h2);
                mma_bf16(s[np*2],   aqh[ks], l0, l2);
                mma_bf16(s[np*2],   aql[ks], h0, h2);
                mma_bf16(s[np*2+1], aqh[ks], h1, h3);
                mma_bf16(s[np*2+1], aqh[ks], l1, l3);
                mma_bf16(s[np*2+1], aql[ks], h1, h3);
            }
        }

        // scale + causal mask
        const float sc = 0.125f;  // 1/sqrt(64)
        if (jt == qt) {
            int r0 = qrow0 + (lane >> 2);
            #pragma unroll
            for (int nf = 0; nf < 8; nf++) {
                int cg = jt*64 + nf*8 + 2*(lane & 3);
                s[nf][0] = (cg     <= r0    ) ? s[nf][0]*sc : -1e30f;
                s[nf][1] = (cg + 1 <= r0    ) ? s[nf][1]*sc : -1e30f;
                s[nf][2] = (cg     <= r0 + 8) ? s[nf][2]*sc : -1e30f;
                s[nf][3] = (cg + 1 <= r0 + 8) ? s[nf][3]*sc : -1e30f;
            }
        } else {
            #pragma unroll
            for (int nf = 0; nf < 8; nf++) {
                #pragma unroll
                for (int j = 0; j < 4; j++) s[nf][j] *= sc;
            }
        }

        // online softmax (rows: lane>>2 and +8; row group = 4 lanes, xor 1,2)
        float mx0 = -1e30f, mx1 = -1e30f;
        #pragma unroll
        for (int nf = 0; nf < 8; nf++) {
            mx0 = fmaxf(mx0, fmaxf(s[nf][0], s[nf][1]));
            mx1 = fmaxf(mx1, fmaxf(s[nf][2], s[nf][3]));
        }
        mx0 = fmaxf(mx0, __shfl_xor_sync(0xffffffffu, mx0, 1));
        mx0 = fmaxf(mx0, __shfl_xor_sync(0xffffffffu, mx0, 2));
        mx1 = fmaxf(mx1, __shfl_xor_sync(0xffffffffu, mx1, 1));
        mx1 = fmaxf(mx1, __shfl_xor_sync(0xffffffffu, mx1, 2));
        float mn0 = fmaxf(m_i[0], mx0), mn1 = fmaxf(m_i[1], mx1);
        float f0 = __expf(m_i[0] - mn0), f1 = __expf(m_i[1] - mn1);
        m_i[0] = mn0; m_i[1] = mn1;
        float sum0 = 0.f, sum1 = 0.f;
        #pragma unroll
        for (int nf = 0; nf < 8; nf++) {
            s[nf][0] = __expf(s[nf][0] - mn0); sum0 += s[nf][0];
            s[nf][1] = __expf(s[nf][1] - mn0); sum0 += s[nf][1];
            s[nf][2] = __expf(s[nf][2] - mn1); sum1 += s[nf][2];
            s[nf][3] = __expf(s[nf][3] - mn1); sum1 += s[nf][3];
        }
        sum0 += __shfl_xor_sync(0xffffffffu, sum0, 1);
        sum0 += __shfl_xor_sync(0xffffffffu, sum0, 2);
        sum1 += __shfl_xor_sync(0xffffffffu, sum1, 1);
        sum1 += __shfl_xor_sync(0xffffffffu, sum1, 2);
        l_i[0] = l_i[0]*f0 + sum0;
        l_i[1] = l_i[1]*f1 + sum1;
        #pragma unroll
        for (int nf = 0; nf < 8; nf++) {
            o[nf][0] *= f0; o[nf][1] *= f0;
            o[nf][2] *= f1; o[nf][3] *= f1;
        }

        // P: C-frag -> A-frag repack with split
        unsigned ph[4][4], pl[4][4];
        #pragma unroll
        for (int kp = 0; kp < 4; kp++) {
            split_pack2(s[kp*2  ][0], s[kp*2  ][1], ph[kp][0], pl[kp][0]);
            split_pack2(s[kp*2  ][2], s[kp*2  ][3], ph[kp][1], pl[kp][1]);
            split_pack2(s[kp*2+1][0], s[kp*2+1][1], ph[kp][2], pl[kp][2]);
            split_pack2(s[kp*2+1][2], s[kp*2+1][3], ph[kp][3], pl[kp][3]);
        }

        // O += P V
        #pragma unroll
        for (int kp = 0; kp < 4; kp++) {
            #pragma unroll
            for (int nq = 0; nq < 4; nq++) {
                int row = kp*16 + (lane & 15);            // kv index
                int col = nq*16 + ((lane >> 4) << 3);     // hd index
                unsigned h0,h1,h2,h3,l0,l1,l2,l3;
                ldsm_x4t(h0,h1,h2,h3, &Vh[row*KST + col]); // r0=b0[2nq] r1=b1[2nq] r2=b0[2nq+1] r3=b1[2nq+1]
                ldsm_x4t(l0,l1,l2,l3, &Vl[row*KST + col]);
                mma_bf16(o[nq*2],   ph[kp], h0, h1);
                mma_bf16(o[nq*2],   ph[kp], l0, l1);
                mma_bf16(o[nq*2],   pl[kp], h0, h1);
                mma_bf16(o[nq*2+1], ph[kp], h2, h3);
                mma_bf16(o[nq*2+1], ph[kp], l2, l3);
                mma_bf16(o[nq*2+1], pl[kp], h2, h3);
            }
        }
    }

    // epilogue: normalize, split, store
    float inv0 = 1.f / l_i[0], inv1 = 1.f / l_i[1];
    int r = lane >> 2, c = 2*(lane & 3);
    size_t base0 = ((size_t)bh*Sx + qrow0 + r    )*HDx;
    size_t base1 = ((size_t)bh*Sx + qrow0 + r + 8)*HDx;
    #pragma unroll
    for (int nf = 0; nf < 8; nf++) {
        int col = nf*8 + c;
        unsigned hi, lo;
        split_pack2(o[nf][0]*inv0, o[nf][1]*inv0, hi, lo);
        *reinterpret_cast<unsigned*>(g_oh + base0 + col) = hi;
        *reinterpret_cast<unsigned*>(g_ol + base0 + col) = lo;
        split_pack2(o[nf][2]*inv1, o[nf][3]*inv1, hi, lo);
        *reinterpret_cast<unsigned*>(g_oh + base1 + col) = hi;
        *reinterpret_cast<unsigned*>(g_ol + base1 + col) = lo;
    }
}

// ---------------------------------------------------------------------------
// Output projection: out = concat_heads(o) @ Wp + bp. A pre-split in g_oh/g_ol.
// ---------------------------------------------------------------------------
__global__ __launch_bounds__(256) void proj_mma(
    const float* __restrict__ Wp, const float* __restrict__ bp,
    float* __restrict__ out)
{
    __shared__ __nv_bfloat16 Ah[128*XST], Al[128*XST];
    __shared__ __nv_bfloat16 Bh[32*WST],  Bl[32*WST];

    const int m0 = blockIdx.x * 128;
    const int n0 = blockIdx.y * 64;
    const int tid = threadIdx.x;
    const int lane = tid & 31, wid = tid >> 5;
    const int wm = (wid >> 1) * 32, wn = (wid & 1) * 32;

    float acc[2][4][4];
    #pragma unroll
    for (int b=0;b<2;b++){
        #pragma unroll
        for (int c2=0;c2<4;c2++){
            #pragma unroll
            for (int d=0;d<4;d++) acc[b][c2][d]=0.f;
        }
    }

    for (int k0 = 0; k0 < Dx; k0 += 32) {
        __syncthreads();
        int hh = k0 >> 6, e0 = k0 & 63;   // head, offset within head (BK=32 stays in-head)
        #pragma unroll
        for (int i = 0; i < 2; i++) {
            int v = tid + i*256;                  // 0..511
            int r = v >> 2, c = (v & 3) << 3;     // 4 chunks of 8 bf16 per row
            int gr = m0 + r, b = gr >> 11, s = gr & 2047;
            size_t ga = ((size_t)(b*Hx + hh)*Sx + s)*HDx + e0 + c;
            *(float4*)&Ah[r*XST + c] = *(const float4*)(g_oh + ga);
            *(float4*)&Al[r*XST + c] = *(const float4*)(g_ol + ga);
        }
        #pragma unroll
        for (int i = 0; i < 2; i++) {
            int v = tid + i*256;
            int r = v >> 4, c = (v & 15) << 2;
            float4 t = *(const float4*)(Wp + (size_t)(k0 + r)*Dx + n0 + c);
            split_store4(&Bh[r*WST + c], &Bl[r*WST + c], t);
        }
        __syncthreads();

        #pragma unroll
        for (int ks = 0; ks < 32; ks += 16) {
            unsigned ah[2][4], al[2][4];
            #pragma unroll
            for (int mi = 0; mi < 2; mi++) {
                int row = wm + mi*16 + (lane & 15);
                int col = ks + ((lane >> 4) << 3);
                ldsm_x4(ah[mi][0],ah[mi][1],ah[mi][2],ah[mi][3], &Ah[row*XST + col]);
                ldsm_x4(al[mi][0],al[mi][1],al[mi][2],al[mi][3], &Al[row*XST + col]);
            }
            unsigned bh2[4][2], bl2[4][2];
            #pragma unroll
            for (int np = 0; np < 2; np++) {
                int row = ks + (lane & 15);
                int col = wn + np*16 + ((lane >> 4) << 3);
                unsigned r0,r1,r2,r3;
                ldsm_x4t(r0,r1,r2,r3, &Bh[row*WST + col]);
                bh2[np*2][0]=r0; bh2[np*2][1]=r1; bh2[np*2+1][0]=r2; bh2[np*2+1][1]=r3;
                ldsm_x4t(r0,r1,r2,r3, &Bl[row*WST + col]);
                bl2[np*2][0]=r0; bl2[np*2][1]=r1; bl2[np*2+1][0]=r2; bl2[np*2+1][1]=r3;
            }
            #pragma unroll
            for (int mi = 0; mi < 2; mi++) {
                #pragma unroll
                for (int nf = 0; nf < 4; nf++) {
                    mma_bf16(acc[mi][nf], ah[mi], bh2[nf][0], bh2[nf][1]);
                    mma_bf16(acc[mi][nf], ah[mi], bl2[nf][0], bl2[nf][1]);
                    mma_bf16(acc[mi][nf], al[mi], bh2[nf][0], bh2[nf][1]);
                }
            }
        }
    }

    #pragma unroll
    for (int mi = 0; mi < 2; mi++) {
        int row = m0 + wm + mi*16 + (lane >> 2);
        #pragma unroll
        for (int half = 0; half < 2; half++) {
            int rr = row + half*8;
            #pragma unroll
            for (int nf = 0; nf < 4; nf++) {
                int col = n0 + wn + nf*8 + 2*(lane & 3);
                float2 v;
                v.x = acc[mi][nf][half*2+0] + bp[col];
                v.y = acc[mi][nf][half*2+1] + bp[col+1];
                *(float2*)(out + (size_t)rr*Dx + col) = v;
            }
        }
    }
}

// ---------------------------------------------------------------------------
extern "C" void kernel_launch(void* const* d_in, const int* in_sizes, int n_in,
                              void* d_out, int out_size)
{
    const float* x  = (const float*)d_in[0];
    const float* Wq = (const float*)d_in[1];
    const float* bq = (const float*)d_in[2];
    const float* Wk = (const float*)d_in[3];
    const float* bk = (const float*)d_in[4];
    const float* Wv = (const float*)d_in[5];
    const float* bv = (const float*)d_in[6];
    const float* Wp = (const float*)d_in[7];
    const float* bp = (const float*)d_in[8];
    float* out = (float*)d_out;

    qkv_mma<<<dim3(Mx/128, Hx), 256>>>(x, Wq, bq, Wk, bk, Wv, bv);
    attn_mma<<<dim3(Sx/64, Bx*Hx), 128>>>();
    proj_mma<<<dim3(Mx/128, Dx/64), 256>>>(Wp, bp, out);
}